// round 8
// baseline (speedup 1.0000x reference)
#include <cuda_runtime.h>
#include <cstdint>

#define N_VERTS 262144
#define N_PAIRS 8388608
#define DHAT2 0.0025f
#define EPSF 1e-12f

#define MAIN_BLOCK 256
#define MAIN_GRID 2048
// n4 = N_PAIRS/4 = 2097152 = 4 * (MAIN_GRID*MAIN_BLOCK) exactly -> 16 pairs/thread.

// Scratch: current coordinates (rest + displacement), fits in L2 (2 MB).
__device__ float2 g_coords[N_VERTS];

// ---------------------------------------------------------------------------
// Kernel A: coords = rest + Uu.reshape(-1,2); zero the output scalar.
// ---------------------------------------------------------------------------
__global__ void __launch_bounds__(512)
build_coords_kernel(const float4* __restrict__ Uu,
                    const float4* __restrict__ rest,
                    float* __restrict__ out) {
    int i = blockIdx.x * blockDim.x + threadIdx.x;  // indexes vert pairs
    if (i < N_VERTS / 2) {
        float4 r = __ldg(&rest[i]);
        float4 u = __ldg(&Uu[i]);
        float4 c = make_float4(r.x + u.x, r.y + u.y, r.z + u.z, r.w + u.w);
        reinterpret_cast<float4*>(g_coords)[i] = c;
    }
    if (blockIdx.x == 0 && threadIdx.x == 0) {
        out[0] = 0.0f;  // d_out is poisoned; initialize
    }
}

// ---------------------------------------------------------------------------
// Barrier math on already-gathered coords (reference math, fp32, fast
// log/div; rel tolerance 1e-3 vs __logf error ~5e-7).
// ---------------------------------------------------------------------------
__device__ __forceinline__ float barrier_term(float2 p, float2 a, float2 b) {
    float abx = b.x - a.x, aby = b.y - a.y;
    float apx = p.x - a.x, apy = p.y - a.y;
    float denom = abx * abx + aby * aby;
    float t = __fdividef(apx * abx + apy * aby, fmaxf(denom, EPSF));
    t = fminf(fmaxf(t, 0.0f), 1.0f);
    float dx = apx - t * abx;
    float dy = apy - t * aby;
    float d2 = dx * dx + dy * dy;

    if (d2 < DHAT2) {
        float d2s = fmaxf(d2, EPSF);
        float m = d2s - DHAT2;
        return -(m * m) * __logf(d2s * (1.0f / DHAT2));
    }
    return 0.0f;
}

// ---------------------------------------------------------------------------
// Kernel B: PDL secondary. Phase 1: stream all 12 int4 index vectors (the
// thread's 16 pairs) while kernel A runs. Phase 2 (post grid-dep sync):
// issue ALL 48 random gathers as one batch (just under the ~55/warp
// outstanding-LDG cap), then compute. 2 blocks/SM via launch_bounds.
// ---------------------------------------------------------------------------
__global__ void __launch_bounds__(MAIN_BLOCK, 2)
barrier_energy_kernel(const int4* __restrict__ pv4,
                      const int4* __restrict__ pe04,
                      const int4* __restrict__ pe14,
                      float* __restrict__ out) {
    const int S = MAIN_GRID * MAIN_BLOCK;  // 524288
    int tid = blockIdx.x * MAIN_BLOCK + threadIdx.x;

    // Phase 1: coalesced streaming index prefetch — independent of kernel A.
    int4 v4[4], e04[4], e14[4];
    #pragma unroll
    for (int g = 0; g < 4; g++) {
        v4[g]  = __ldcs(&pv4[tid + g * S]);
        e04[g] = __ldcs(&pe04[tid + g * S]);
        e14[g] = __ldcs(&pe14[tid + g * S]);
    }

    // Unpack to flat index arrays (registers).
    int iv[16], i0[16], i1[16];
    #pragma unroll
    for (int g = 0; g < 4; g++) {
        iv[4*g+0] = v4[g].x;  iv[4*g+1] = v4[g].y;  iv[4*g+2] = v4[g].z;  iv[4*g+3] = v4[g].w;
        i0[4*g+0] = e04[g].x; i0[4*g+1] = e04[g].y; i0[4*g+2] = e04[g].z; i0[4*g+3] = e04[g].w;
        i1[4*g+0] = e14[g].x; i1[4*g+1] = e14[g].y; i1[4*g+2] = e14[g].z; i1[4*g+3] = e14[g].w;
    }

    // Wait for kernel A (g_coords) to be complete and visible.
    cudaGridDependencySynchronize();

    // Phase 2: one maximal gather batch — 48 independent random loads.
    float2 cp[16], ca[16], cb[16];
    #pragma unroll
    for (int k = 0; k < 16; k++) {
        cp[k] = __ldg(&g_coords[iv[k]]);
        ca[k] = __ldg(&g_coords[i0[k]]);
        cb[k] = __ldg(&g_coords[i1[k]]);
    }

    // Compute all 16 barrier terms.
    float s = 0.0f;
    double acc = 0.0;
    #pragma unroll
    for (int k = 0; k < 16; k++) {
        s += barrier_term(cp[k], ca[k], cb[k]);
        if ((k & 3) == 3) { acc += (double)s; s = 0.0f; }  // bounded fp32 chains
    }

    // Warp reduction
    #pragma unroll
    for (int off = 16; off > 0; off >>= 1)
        acc += __shfl_xor_sync(0xFFFFFFFFu, acc, off);

    __shared__ double warp_sums[MAIN_BLOCK / 32];
    int lane = threadIdx.x & 31;
    int wid = threadIdx.x >> 5;
    if (lane == 0) warp_sums[wid] = acc;
    __syncthreads();

    if (wid == 0) {
        double vsum = (lane < (MAIN_BLOCK / 32)) ? warp_sums[lane] : 0.0;
        #pragma unroll
        for (int off = 4; off > 0; off >>= 1)
            vsum += __shfl_xor_sync(0xFFFFFFFFu, vsum, off);
        if (lane == 0)
            atomicAdd(out, (float)vsum);
    }
}

// ---------------------------------------------------------------------------
extern "C" void kernel_launch(void* const* d_in, const int* in_sizes, int n_in,
                              void* d_out, int out_size) {
    const float4* Uu   = (const float4*)d_in[0];
    const float4* rest = (const float4*)d_in[1];
    const int4* pv  = (const int4*)d_in[2];
    const int4* pe0 = (const int4*)d_in[3];
    const int4* pe1 = (const int4*)d_in[4];
    float* out = (float*)d_out;

    build_coords_kernel<<<(N_VERTS / 2 + 511) / 512, 512>>>(Uu, rest, out);

    // PDL launch: B starts while A runs; B blocks at
    // cudaGridDependencySynchronize() until A completes.
    cudaLaunchAttribute attrs[1];
    attrs[0].id = cudaLaunchAttributeProgrammaticStreamSerialization;
    attrs[0].val.programmaticStreamSerializationAllowed = 1;

    cudaLaunchConfig_t cfg = {};
    cfg.gridDim = dim3(MAIN_GRID, 1, 1);
    cfg.blockDim = dim3(MAIN_BLOCK, 1, 1);
    cfg.dynamicSmemBytes = 0;
    cfg.stream = 0;
    cfg.attrs = attrs;
    cfg.numAttrs = 1;

    cudaLaunchKernelEx(&cfg, barrier_energy_kernel, pv, pe0, pe1, out);
}